// round 1
// baseline (speedup 1.0000x reference)
#include <cuda_runtime.h>
#include <math.h>
#include <stdint.h>

#define Bsz   8192
#define DIN   1024
#define Hdim  128
#define Ecnt  8
#define DOUT  1024
#define BKSEL 2048   // ceil(K*B/E) = ceil(2*8192/8)

// ---------------- scratch (device globals; no runtime allocation) ----------
__device__ float g_h[Bsz * Hdim];            // 4 MB  router hidden
__device__ float g_logits[Bsz * Ecnt];       // 256 KB
__device__ int   g_idx[Ecnt][BKSEL];         // selected token index per (e, slot)
__device__ float g_nws[Ecnt][BKSEL];         // renormalized weights
__device__ int   g_sel_slot[Bsz][Ecnt];      // token,expert -> slot or -1
__device__ float g_eo[(size_t)BKSEL * Ecnt * DOUT]; // 64 MB  [slot][e][d]

// ---------------------------------------------------------------------------
// Kernel 1: router hidden h = relu((x@w1+b1) * relu(x@wg+bg))
// 64-row x 128-col tile per block, 256 threads, thread tile 4x8 per matrix.
// ---------------------------------------------------------------------------
__global__ __launch_bounds__(256) void k_router(
    const float* __restrict__ x,
    const float* __restrict__ w1, const float* __restrict__ b1,
    const float* __restrict__ wg, const float* __restrict__ bg)
{
    __shared__ float Xs[16][64];
    __shared__ float W1s[16][128];
    __shared__ float WGs[16][128];

    const int tid = threadIdx.x;
    const int tx  = tid & 15;     // col lane
    const int ty  = tid >> 4;     // row lane
    const int row0 = blockIdx.x * 64;

    float acc1[4][8];
    float accg[4][8];
#pragma unroll
    for (int i = 0; i < 4; i++)
#pragma unroll
        for (int j = 0; j < 8; j++) { acc1[i][j] = 0.f; accg[i][j] = 0.f; }

    for (int k0 = 0; k0 < DIN; k0 += 16) {
        // X tile: 64 rows x 16 k = 1024 floats -> 256 threads x 1 float4
        {
            int lin = tid;
            int m  = lin >> 2;
            int kq = (lin & 3) << 2;
            float4 v = *(const float4*)(x + (size_t)(row0 + m) * DIN + k0 + kq);
            Xs[kq + 0][m] = v.x; Xs[kq + 1][m] = v.y;
            Xs[kq + 2][m] = v.z; Xs[kq + 3][m] = v.w;
        }
        // W tiles: 16 x 128 each = 512 float4 -> 2 per thread
#pragma unroll
        for (int r = 0; r < 2; r++) {
            int lin = tid + r * 256;
            int kk  = lin >> 5;
            int nq  = (lin & 31) << 2;
            *(float4*)&W1s[kk][nq] = *(const float4*)(w1 + (size_t)(k0 + kk) * Hdim + nq);
            *(float4*)&WGs[kk][nq] = *(const float4*)(wg + (size_t)(k0 + kk) * Hdim + nq);
        }
        __syncthreads();
#pragma unroll
        for (int kk = 0; kk < 16; kk++) {
            float xr[4], w1r[8], wgr[8];
#pragma unroll
            for (int i = 0; i < 4; i++) xr[i] = Xs[kk][i * 16 + ty];
#pragma unroll
            for (int j = 0; j < 8; j++) {
                w1r[j] = W1s[kk][j * 16 + tx];
                wgr[j] = WGs[kk][j * 16 + tx];
            }
#pragma unroll
            for (int i = 0; i < 4; i++)
#pragma unroll
                for (int j = 0; j < 8; j++) {
                    acc1[i][j] = fmaf(xr[i], w1r[j], acc1[i][j]);
                    accg[i][j] = fmaf(xr[i], wgr[j], accg[i][j]);
                }
        }
        __syncthreads();
    }
#pragma unroll
    for (int i = 0; i < 4; i++) {
        int r = row0 + i * 16 + ty;
#pragma unroll
        for (int j = 0; j < 8; j++) {
            int n = j * 16 + tx;
            float a = acc1[i][j] + b1[n];
            float g = accg[i][j] + bg[n];
            g = fmaxf(g, 0.f);
            float hv = fmaxf(a * g, 0.f);
            g_h[(size_t)r * Hdim + n] = hv;
        }
    }
}

// ---------------------------------------------------------------------------
// Kernel 2: logits = h @ w2 + b2   (one thread per token row)
// ---------------------------------------------------------------------------
__global__ __launch_bounds__(256) void k_logits(
    const float* __restrict__ w2, const float* __restrict__ b2)
{
    __shared__ float W2s[Hdim * Ecnt];
    const int tid = threadIdx.x;
    for (int i = tid; i < Hdim * Ecnt; i += 256) W2s[i] = w2[i];
    __syncthreads();

    const int b = blockIdx.x * 256 + tid;
    float acc[Ecnt];
#pragma unroll
    for (int e = 0; e < Ecnt; e++) acc[e] = b2[e];
    const float* hr = g_h + (size_t)b * Hdim;
#pragma unroll 4
    for (int k = 0; k < Hdim; k++) {
        float hv = hr[k];
#pragma unroll
        for (int e = 0; e < Ecnt; e++) acc[e] = fmaf(hv, W2s[k * Ecnt + e], acc[e]);
    }
#pragma unroll
    for (int e = 0; e < Ecnt; e++) g_logits[(size_t)b * Ecnt + e] = acc[e];
}

// ---------------------------------------------------------------------------
// Kernel 3: per expert — column softmax over batch, exact top-2048 selection
// (radix bisection on float bits, lowest-index tie-break), renorm softmax.
// One block per expert, 1024 threads.
// ---------------------------------------------------------------------------
__global__ __launch_bounds__(1024) void k_select()
{
    __shared__ float lv[Bsz];      // 32 KB softmax values for this column
    __shared__ float redf[1024];
    __shared__ int   redi[1024];
    __shared__ unsigned s_cnt;
    __shared__ float s_bf;
    __shared__ int   s_bi;

    const int e   = blockIdx.x;
    const int tid = threadIdx.x;

    float loc[8];
#pragma unroll
    for (int r = 0; r < 8; r++) {
        int i = tid + r * 1024;
        loc[r] = g_logits[(size_t)i * Ecnt + e];
        g_sel_slot[i][e] = -1;
    }

    // --- column max ---
    float m = -1e30f;
#pragma unroll
    for (int r = 0; r < 8; r++) m = fmaxf(m, loc[r]);
    redf[tid] = m; __syncthreads();
    for (int s = 512; s > 0; s >>= 1) {
        if (tid < s) redf[tid] = fmaxf(redf[tid], redf[tid + s]);
        __syncthreads();
    }
    if (tid == 0) s_bf = redf[0];
    __syncthreads();
    m = s_bf;
    __syncthreads();

    // --- column sum of exp ---
    float s = 0.f;
#pragma unroll
    for (int r = 0; r < 8; r++) s += expf(loc[r] - m);
    redf[tid] = s; __syncthreads();
    for (int st = 512; st > 0; st >>= 1) {
        if (tid < st) redf[tid] += redf[tid + st];
        __syncthreads();
    }
    if (tid == 0) s_bf = redf[0];
    __syncthreads();
    s = s_bf;
    __syncthreads();

    const float inv_s = 1.0f / s;
#pragma unroll
    for (int r = 0; r < 8; r++) lv[tid + r * 1024] = expf(loc[r] - m) * inv_s;
    __syncthreads();

    // --- radix bisection: V = 2048th largest value (as uint bits; all >= 0) ---
    unsigned cur = 0u;
    for (int bit = 31; bit >= 0; bit--) {
        unsigned cand = cur | (1u << bit);
        int c = 0;
#pragma unroll
        for (int r = 0; r < 8; r++)
            c += (__float_as_uint(lv[tid + r * 1024]) >= cand) ? 1 : 0;
        redi[tid] = c; __syncthreads();
        for (int st = 512; st > 0; st >>= 1) {
            if (tid < st) redi[tid] += redi[tid + st];
            __syncthreads();
        }
        if (tid == 0) s_bi = redi[0];
        __syncthreads();
        if (s_bi >= BKSEL) cur = cand;
        __syncthreads();
    }
    const unsigned V = cur;

    // --- collect strictly-greater first (order irrelevant), then equals by
    //     ascending index (matches jax.lax.top_k tie-break) ---
    if (tid == 0) s_cnt = 0u;
    __syncthreads();
#pragma unroll
    for (int r = 0; r < 8; r++) {
        int i = tid + r * 1024;
        if (__float_as_uint(lv[i]) > V) {
            unsigned p = atomicAdd(&s_cnt, 1u);
            g_idx[e][p] = i;
            g_sel_slot[i][e] = (int)p;
        }
    }
    __syncthreads();
    if (tid == 0) {
        unsigned p = s_cnt;
        for (int i = 0; i < Bsz && p < BKSEL; i++) {
            if (__float_as_uint(lv[i]) == V) {
                g_idx[e][p] = i;
                g_sel_slot[i][e] = (int)p;
                p++;
            }
        }
    }
    __syncthreads();

    // --- nws = softmax over the 2048 selected weights ---
    float wsv[2];
    float m2 = -1e30f;
#pragma unroll
    for (int r = 0; r < 2; r++) {
        int slot = tid + r * 1024;
        wsv[r] = lv[g_idx[e][slot]];
        m2 = fmaxf(m2, wsv[r]);
    }
    redf[tid] = m2; __syncthreads();
    for (int st = 512; st > 0; st >>= 1) {
        if (tid < st) redf[tid] = fmaxf(redf[tid], redf[tid + st]);
        __syncthreads();
    }
    if (tid == 0) s_bf = redf[0];
    __syncthreads();
    m2 = s_bf;
    __syncthreads();

    float s2 = expf(wsv[0] - m2) + expf(wsv[1] - m2);
    redf[tid] = s2; __syncthreads();
    for (int st = 512; st > 0; st >>= 1) {
        if (tid < st) redf[tid] += redf[tid + st];
        __syncthreads();
    }
    if (tid == 0) s_bf = redf[0];
    __syncthreads();
    s2 = s_bf;

    const float inv_s2 = 1.0f / s2;
#pragma unroll
    for (int r = 0; r < 2; r++)
        g_nws[e][tid + r * 1024] = expf(wsv[r] - m2) * inv_s2;
}

// ---------------------------------------------------------------------------
// Kernel 4: expert GEMM with gathered rows:
//   eo[slot, e, :] = (x[idx[e][slot]] @ we[e] + be[e]) * nws[e][slot]
// 128x128 tile / block, 256 threads, 8x8 thread tile, fp32.
// ---------------------------------------------------------------------------
__global__ __launch_bounds__(256) void k_expert(
    const float* __restrict__ x,
    const float* __restrict__ we, const float* __restrict__ be)
{
    __shared__ float As[16][128];
    __shared__ float Bs[16][128];
    __shared__ int   ridx[128];

    const int e  = blockIdx.z;
    const int m0 = blockIdx.y * 128;
    const int n0 = blockIdx.x * 128;
    const int tid = threadIdx.x;
    const int tx  = tid & 15;
    const int ty  = tid >> 4;

    if (tid < 128) ridx[tid] = g_idx[e][m0 + tid];
    __syncthreads();

    float acc[8][8];
#pragma unroll
    for (int i = 0; i < 8; i++)
#pragma unroll
        for (int j = 0; j < 8; j++) acc[i][j] = 0.f;

    const float* weE = we + (size_t)e * DIN * DOUT;

    for (int k0 = 0; k0 < DIN; k0 += 16) {
        // A tile: 128 rows x 16 k = 512 float4, gathered
#pragma unroll
        for (int r = 0; r < 2; r++) {
            int lin = tid + r * 256;
            int mm  = lin >> 2;
            int kq  = (lin & 3) << 2;
            float4 v = *(const float4*)(x + (size_t)ridx[mm] * DIN + k0 + kq);
            As[kq + 0][mm] = v.x; As[kq + 1][mm] = v.y;
            As[kq + 2][mm] = v.z; As[kq + 3][mm] = v.w;
        }
        // B tile: 16 k x 128 n = 512 float4, coalesced
#pragma unroll
        for (int r = 0; r < 2; r++) {
            int lin = tid + r * 256;
            int kk  = lin >> 5;
            int nq  = (lin & 31) << 2;
            *(float4*)&Bs[kk][nq] =
                *(const float4*)(weE + (size_t)(k0 + kk) * DOUT + n0 + nq);
        }
        __syncthreads();
#pragma unroll
        for (int kk = 0; kk < 16; kk++) {
            float ar[8], br[8];
#pragma unroll
            for (int i = 0; i < 8; i++) ar[i] = As[kk][i * 16 + ty];
#pragma unroll
            for (int j = 0; j < 8; j++) br[j] = Bs[kk][j * 16 + tx];
#pragma unroll
            for (int i = 0; i < 8; i++)
#pragma unroll
                for (int j = 0; j < 8; j++)
                    acc[i][j] = fmaf(ar[i], br[j], acc[i][j]);
        }
        __syncthreads();
    }

#pragma unroll
    for (int i = 0; i < 8; i++) {
        int slot = m0 + i * 16 + ty;
        float nw = g_nws[e][slot];
        float* orow = g_eo + ((size_t)slot * Ecnt + e) * DOUT + n0;
#pragma unroll
        for (int j = 0; j < 8; j++) {
            int n = j * 16 + tx;
            orow[n] = (acc[i][j] + be[(size_t)e * DOUT + n0 + n]) * nw;
        }
    }
}

// ---------------------------------------------------------------------------
// Kernel 5: combine. For token row b:
//   c_e = eo[slot(b,e), e, :] if selected else 0
//   out[b, e*DOUT + d] = c_e[d] + sum_e' c_e'[d]
// No atomics needed: temp_sum is exactly the per-row sum over experts.
// ---------------------------------------------------------------------------
__global__ __launch_bounds__(256) void k_combine(float* __restrict__ out)
{
    __shared__ int slots[Ecnt];
    const int b   = blockIdx.x;
    const int tid = threadIdx.x;
    if (tid < Ecnt) slots[tid] = g_sel_slot[b][tid];
    __syncthreads();

#pragma unroll
    for (int r = 0; r < 4; r++) {
        int d = tid + r * 256;
        float c[Ecnt];
        float ssum = 0.f;
#pragma unroll
        for (int e = 0; e < Ecnt; e++) {
            int slot = slots[e];
            float v = 0.f;
            if (slot >= 0) v = g_eo[((size_t)slot * Ecnt + e) * DOUT + d];
            c[e] = v;
            ssum += v;
        }
        float* orow = out + (size_t)b * (Ecnt * DOUT) + d;
#pragma unroll
        for (int e = 0; e < Ecnt; e++)
            orow[(size_t)e * DOUT] = c[e] + ssum;
    }
}

// ---------------------------------------------------------------------------
extern "C" void kernel_launch(void* const* d_in, const int* in_sizes, int n_in,
                              void* d_out, int out_size)
{
    const float* x  = (const float*)d_in[0];
    const float* w1 = (const float*)d_in[1];
    const float* b1 = (const float*)d_in[2];
    const float* wg = (const float*)d_in[3];
    const float* bg = (const float*)d_in[4];
    const float* w2 = (const float*)d_in[5];
    const float* b2 = (const float*)d_in[6];
    const float* we = (const float*)d_in[7];
    const float* be = (const float*)d_in[8];
    float* out = (float*)d_out;

    k_router<<<Bsz / 64, 256>>>(x, w1, b1, wg, bg);
    k_logits<<<Bsz / 256, 256>>>(w2, b2);
    k_select<<<Ecnt, 1024>>>();
    k_expert<<<dim3(DOUT / 128, BKSEL / 128, Ecnt), 256>>>(x, we, be);
    k_combine<<<Bsz, 256>>>(out);
}